// round 1
// baseline (speedup 1.0000x reference)
#include <cuda_runtime.h>
#include <math.h>

// ---------------------------------------------------------------------------
// VQ-VAE forward.  B=16, L=156, P=8, H=W=128, codebook 512x8.
// Pipeline: conv156->128 relu, conv128->64 relu, conv64->8 relu,
//           VQ (groups of 8 along W!), convT 8->64 relu, convT 64->128 relu,
//           convT 128->156 sigmoid, plus vq_loss = 1.25*mean((q-z)^2).
// ---------------------------------------------------------------------------

#define BATCH 16
#define HW    16384   // 128*128

// Static device scratch (allocation-free rule).
__device__ float g_z1[BATCH * 128 * HW];   // 134 MB
__device__ float g_z2[BATCH *  64 * HW];   //  67 MB
__device__ float g_z3[BATCH *   8 * HW];   //   8 MB
__device__ float g_q [BATCH *   8 * HW];   //   8 MB
__device__ float g_y1[BATCH *  64 * HW];   //  67 MB
__device__ float g_y2[BATCH * 128 * HW];   // 134 MB
__device__ float g_w1e[64 * 8 * 9];
__device__ float g_w2e[128 * 64 * 9];
__device__ float g_w3e[156 * 128 * 9];
__device__ double g_part[256];

// ---------------------------------------------------------------------------
// ConvTranspose weight -> equivalent forward-conv weight:
//   w_eff[o][i][kh][kw] = w[i][o][2-kh][2-kw]      (w is [IN][OUT][3][3])
// ---------------------------------------------------------------------------
__global__ void transpose_wt(const float* __restrict__ w, float* __restrict__ weff,
                             int IN, int OUT) {
    int i = blockIdx.x * blockDim.x + threadIdx.x;
    int total = IN * OUT * 9;
    if (i >= total) return;
    int kw = i % 3;
    int kh = (i / 3) % 3;
    int o  = (i / 9) % OUT;
    int ii = i / (9 * OUT);
    weff[((o * IN + ii) * 3 + (2 - kh)) * 3 + (2 - kw)] = w[i];
}

// ---------------------------------------------------------------------------
// 3x3 same-conv, NCHW, fp32.  Block = (n, row h, MT output channels).
// 256 threads: lane (0..31) = w-group (w = lane + k*32, k=0..3, stride-32
// mapping -> conflict-free smem loads), cg (0..7) = co-group, NCO=MT/8
// channels per thread.  Input staged per 8-channel chunk.
// ACT: 0 none, 1 relu, 2 sigmoid.
// ---------------------------------------------------------------------------
template<int CIN, int COUT, int MT, int ACT>
__global__ __launch_bounds__(256)
void conv3x3(const float* __restrict__ in, const float* __restrict__ wt,
             const float* __restrict__ bias, float* __restrict__ out) {
    constexpr int KC  = 8;
    constexpr int NCO = MT / 8;

    __shared__ float s_in[KC][3][132];   // 130 valid cols (+pad)
    __shared__ float s_w [MT][KC * 9];

    const int n       = blockIdx.z;
    const int h       = blockIdx.x;
    const int co_base = blockIdx.y * MT;
    const int tid     = threadIdx.x;
    const int lane    = tid & 31;
    const int cg      = tid >> 5;

    float acc[NCO][4];
#pragma unroll
    for (int c = 0; c < NCO; c++)
#pragma unroll
        for (int k = 0; k < 4; k++) acc[c][k] = 0.f;

    const float* inN = in + (size_t)n * CIN * HW;

    for (int c0 = 0; c0 < CIN; c0 += KC) {
        // ---- stage input slab: KC channels x 3 rows x 130 cols (halo+pad)
        for (int i = tid; i < KC * 3 * 130; i += 256) {
            int kc  = i / 390;
            int rem = i % 390;
            int r   = rem / 130;
            int c   = rem % 130;
            int ci  = c0 + kc;
            int gh  = h - 1 + r;
            int gc  = c - 1;
            float v = 0.f;
            if (ci < CIN && gh >= 0 && gh < 128 && gc >= 0 && gc < 128)
                v = inN[(size_t)ci * HW + gh * 128 + gc];
            s_in[kc][r][c] = v;
        }
        // ---- stage weights: MT co x KC ci x 9 taps
        for (int i = tid; i < MT * KC * 9; i += 256) {
            int mt  = i / (KC * 9);
            int rem = i % (KC * 9);
            int kc  = rem / 9;
            int tap = rem % 9;
            int co  = co_base + mt;
            int ci  = c0 + kc;
            float v = 0.f;
            if (co < COUT && ci < CIN)
                v = wt[((size_t)co * CIN + ci) * 9 + tap];
            s_w[mt][rem] = v;
        }
        __syncthreads();

        for (int kc = 0; kc < KC; kc++) {
#pragma unroll
            for (int dh = 0; dh < 3; dh++) {
                float xin[12];
#pragma unroll
                for (int k = 0; k < 4; k++)
#pragma unroll
                    for (int d = 0; d < 3; d++)
                        xin[k * 3 + d] = s_in[kc][dh][lane + k * 32 + d];
#pragma unroll
                for (int dw = 0; dw < 3; dw++) {
#pragma unroll
                    for (int c = 0; c < NCO; c++) {
                        float wv = s_w[cg * NCO + c][kc * 9 + dh * 3 + dw];
#pragma unroll
                        for (int k = 0; k < 4; k++)
                            acc[c][k] = fmaf(wv, xin[k * 3 + dw], acc[c][k]);
                    }
                }
            }
        }
        __syncthreads();
    }

#pragma unroll
    for (int c = 0; c < NCO; c++) {
        int co = co_base + cg * NCO + c;
        if (co < COUT) {
            float b = bias[co];
#pragma unroll
            for (int k = 0; k < 4; k++) {
                float v = acc[c][k] + b;
                if (ACT == 1) v = fmaxf(v, 0.f);
                else if (ACT == 2) v = 1.f / (1.f + __expf(-v));
                out[((size_t)n * COUT + co) * HW + h * 128 + lane + k * 32] = v;
            }
        }
    }
}

// ---------------------------------------------------------------------------
// Vector quantizer.  z flat in groups of 8 consecutive floats (torch .view
// semantics on NCHW!).  262144 vectors, 512 codes, dim 8.
// argmin_k ||v-e_k||^2  ==  argmin_k (0.5||e_k||^2 - v.e_k); strict '<'
// keeps first-min semantics.  4 vectors per thread, 256 blocks x 256 thr.
// Deterministic loss: per-block partial into fixed slot.
// ---------------------------------------------------------------------------
__global__ __launch_bounds__(256)
void vq_kernel(const float* __restrict__ z, const float* __restrict__ emb,
               float* __restrict__ q, double* __restrict__ part) {
    __shared__ float  s_e[512 * 8];
    __shared__ float  s_hn[512];
    __shared__ double s_red[256];

    const int tid = threadIdx.x;
    for (int i = tid; i < 4096; i += 256) s_e[i] = emb[i];
    __syncthreads();
    for (int k = tid; k < 512; k += 256) {
        float s = 0.f;
#pragma unroll
        for (int j = 0; j < 8; j++) { float e = s_e[k * 8 + j]; s += e * e; }
        s_hn[k] = 0.5f * s;
    }
    __syncthreads();

    const int base = blockIdx.x * 1024 + tid;   // vectors: base + u*256
    float v[4][8];
#pragma unroll
    for (int u = 0; u < 4; u++) {
        int vi = base + u * 256;
        float4 a = ((const float4*)z)[vi * 2];
        float4 b = ((const float4*)z)[vi * 2 + 1];
        v[u][0] = a.x; v[u][1] = a.y; v[u][2] = a.z; v[u][3] = a.w;
        v[u][4] = b.x; v[u][5] = b.y; v[u][6] = b.z; v[u][7] = b.w;
    }

    float best[4] = {3.4e38f, 3.4e38f, 3.4e38f, 3.4e38f};
    int   bk[4]   = {0, 0, 0, 0};
    for (int k = 0; k < 512; k++) {
        float e0 = s_e[k * 8 + 0], e1 = s_e[k * 8 + 1], e2 = s_e[k * 8 + 2], e3 = s_e[k * 8 + 3];
        float e4 = s_e[k * 8 + 4], e5 = s_e[k * 8 + 5], e6 = s_e[k * 8 + 6], e7 = s_e[k * 8 + 7];
        float hn = s_hn[k];
#pragma unroll
        for (int u = 0; u < 4; u++) {
            float dot = e0 * v[u][0] + e1 * v[u][1] + e2 * v[u][2] + e3 * v[u][3]
                      + e4 * v[u][4] + e5 * v[u][5] + e6 * v[u][6] + e7 * v[u][7];
            float sc = hn - dot;
            if (sc < best[u]) { best[u] = sc; bk[u] = k; }
        }
    }

    float sq = 0.f;
#pragma unroll
    for (int u = 0; u < 4; u++) {
        int vi = base + u * 256;
        int kb = bk[u];
        float4 o1, o2;
        o1.x = s_e[kb * 8 + 0]; o1.y = s_e[kb * 8 + 1];
        o1.z = s_e[kb * 8 + 2]; o1.w = s_e[kb * 8 + 3];
        o2.x = s_e[kb * 8 + 4]; o2.y = s_e[kb * 8 + 5];
        o2.z = s_e[kb * 8 + 6]; o2.w = s_e[kb * 8 + 7];
#pragma unroll
        for (int j = 0; j < 8; j++) {
            float d = s_e[kb * 8 + j] - v[u][j];
            sq += d * d;
        }
        ((float4*)q)[vi * 2]     = o1;
        ((float4*)q)[vi * 2 + 1] = o2;
    }

    s_red[tid] = (double)sq;
    __syncthreads();
    for (int o = 128; o > 0; o >>= 1) {
        if (tid < o) s_red[tid] += s_red[tid + o];
        __syncthreads();
    }
    if (tid == 0) part[blockIdx.x] = s_red[0];
}

__global__ void finalize_loss(const double* __restrict__ part, float* __restrict__ outp) {
    __shared__ double s[256];
    int tid = threadIdx.x;
    s[tid] = part[tid];
    __syncthreads();
    for (int o = 128; o > 0; o >>= 1) {
        if (tid < o) s[tid] += s[tid + o];
        __syncthreads();
    }
    // vq_loss = q_latent + 0.25*e_latent = 1.25 * mean((q-z)^2), mean over 16*8*128*128
    if (tid == 0) *outp = (float)(1.25 * s[0] / 2097152.0);
}

// ---------------------------------------------------------------------------
extern "C" void kernel_launch(void* const* d_in, const int* in_sizes, int n_in,
                              void* d_out, int out_size) {
    (void)in_sizes; (void)n_in;
    const float* x   = (const float*)d_in[0];
    const float* e1w = (const float*)d_in[1];
    const float* e1b = (const float*)d_in[2];
    const float* e2w = (const float*)d_in[3];
    const float* e2b = (const float*)d_in[4];
    const float* e3w = (const float*)d_in[5];
    const float* e3b = (const float*)d_in[6];
    const float* emb = (const float*)d_in[7];
    const float* d1w = (const float*)d_in[8];
    const float* d1b = (const float*)d_in[9];
    const float* d2w = (const float*)d_in[10];
    const float* d2b = (const float*)d_in[11];
    const float* d3w = (const float*)d_in[12];
    const float* d3b = (const float*)d_in[13];
    float* out = (float*)d_out;

    void *z1, *z2, *z3, *q, *y1, *y2, *w1e, *w2e, *w3e, *part;
    cudaGetSymbolAddress(&z1,  g_z1);
    cudaGetSymbolAddress(&z2,  g_z2);
    cudaGetSymbolAddress(&z3,  g_z3);
    cudaGetSymbolAddress(&q,   g_q);
    cudaGetSymbolAddress(&y1,  g_y1);
    cudaGetSymbolAddress(&y2,  g_y2);
    cudaGetSymbolAddress(&w1e, g_w1e);
    cudaGetSymbolAddress(&w2e, g_w2e);
    cudaGetSymbolAddress(&w3e, g_w3e);
    cudaGetSymbolAddress(&part, g_part);

    // decoder weight prep (flip + IO swap)
    transpose_wt<<<(8 * 64 * 9 + 255) / 256, 256>>>(d1w, (float*)w1e, 8, 64);
    transpose_wt<<<(64 * 128 * 9 + 255) / 256, 256>>>(d2w, (float*)w2e, 64, 128);
    transpose_wt<<<(128 * 156 * 9 + 255) / 256, 256>>>(d3w, (float*)w3e, 128, 156);

    // encoder
    conv3x3<156, 128, 64, 1><<<dim3(128, 2, 16), 256>>>(x, e1w, e1b, (float*)z1);
    conv3x3<128,  64, 64, 1><<<dim3(128, 1, 16), 256>>>((float*)z1, e2w, e2b, (float*)z2);
    conv3x3< 64,   8,  8, 1><<<dim3(128, 1, 16), 256>>>((float*)z2, e3w, e3b, (float*)z3);

    // vector quantizer + loss partials
    vq_kernel<<<256, 256>>>((const float*)z3, emb, (float*)q, (double*)part);

    // decoder
    conv3x3<  8,  64, 64, 1><<<dim3(128, 1, 16), 256>>>((float*)q,  (float*)w1e, d1b, (float*)y1);
    conv3x3< 64, 128, 64, 1><<<dim3(128, 2, 16), 256>>>((float*)y1, (float*)w2e, d2b, (float*)y2);
    conv3x3<128, 156, 64, 2><<<dim3(128, 3, 16), 256>>>((float*)y2, (float*)w3e, d3b, out);

    finalize_loss<<<1, 256>>>((const double*)part, out + (out_size - 1));
}

// round 2
// speedup vs baseline: 1.4865x; 1.4865x over previous
#include <cuda_runtime.h>
#include <math.h>

// ---------------------------------------------------------------------------
// VQ-VAE forward.  B=16, L=156, P=8, H=W=128, codebook 512x8.
// R2: packed f32x2 FFMA conv (2 output channels per instruction),
//     2 output rows per block, d3 tail split to kill channel-padding waste.
// ---------------------------------------------------------------------------

#define BATCH 16
#define HW    16384   // 128*128

typedef unsigned long long u64;

__device__ __forceinline__ u64 pack2(float lo, float hi) {
    u64 r; asm("mov.b64 %0, {%1, %2};" : "=l"(r) : "f"(lo), "f"(hi)); return r;
}
__device__ __forceinline__ void fma2(u64 &d, u64 a, u64 b) {
    asm("fma.rn.f32x2 %0, %1, %2, %0;" : "+l"(d) : "l"(a), "l"(b));
}
__device__ __forceinline__ float2 unpk(u64 v) {
    float lo, hi; asm("mov.b64 {%0, %1}, %2;" : "=f"(lo), "=f"(hi) : "l"(v));
    return make_float2(lo, hi);
}

// Static device scratch (allocation-free rule).
__device__ float g_z1[BATCH * 128 * HW];
__device__ float g_z2[BATCH *  64 * HW];
__device__ float g_z3[BATCH *   8 * HW];
__device__ float g_q [BATCH *   8 * HW];
__device__ float g_y1[BATCH *  64 * HW];
__device__ float g_y2[BATCH * 128 * HW];
__device__ float g_w1e[64 * 8 * 9];
__device__ float g_w2e[128 * 64 * 9];
__device__ float g_w3e[156 * 128 * 9];
__device__ double g_part[256];

// ---------------------------------------------------------------------------
// ConvTranspose weight -> forward-conv weight: w_eff[o][i][kh][kw]=w[i][o][2-kh][2-kw]
// ---------------------------------------------------------------------------
__global__ void transpose_wt(const float* __restrict__ w, float* __restrict__ weff,
                             int IN, int OUT) {
    int i = blockIdx.x * blockDim.x + threadIdx.x;
    int total = IN * OUT * 9;
    if (i >= total) return;
    int kw = i % 3;
    int kh = (i / 3) % 3;
    int o  = (i / 9) % OUT;
    int ii = i / (9 * OUT);
    weff[((o * IN + ii) * 3 + (2 - kh)) * 3 + (2 - kw)] = w[i];
}

__device__ __forceinline__ float apply_act(float v, int ACT) {
    if (ACT == 1) return fmaxf(v, 0.f);
    if (ACT == 2) return 1.f / (1.f + __expf(-v));
    return v;
}

// ---------------------------------------------------------------------------
// Packed-f32x2 3x3 same-conv, NCHW fp32.
// Block = (n, row-pair 2h..2h+1, MT output channels starting at CO_OFF+by*MT).
// 256 thr: lane -> 4 consecutive pixels (p0=4*lane), cg=tid>>5 -> co-group.
// f32x2 lanes carry (co, co+1); weights pre-paired in smem as u64.
// ---------------------------------------------------------------------------
template<int CIN, int COUT, int MT, int ACT, int CO_OFF>
__global__ __launch_bounds__(256, 2)
void conv3x3p(const float* __restrict__ in, const float* __restrict__ wt,
              const float* __restrict__ bias, float* __restrict__ out) {
    constexpr int KC   = 8;
    constexpr int NCO  = MT / 8;     // co per thread
    constexpr int NCP  = NCO / 2;    // co-pairs per thread
    constexpr int NCPG = MT / 2;     // co-pairs per block

    __shared__ alignas(16) float s_in[KC][4][132];   // rows h0-1..h0+2, float idx c = col+1
    __shared__ u64 s_w[NCPG][KC * 9];                // {w[co0], w[co0+1]}

    const int n       = blockIdx.z;
    const int h0      = blockIdx.x * 2;
    const int co_base = CO_OFF + blockIdx.y * MT;
    const int tid     = threadIdx.x;
    const int lane    = tid & 31;
    const int cg      = tid >> 5;
    const int p0      = lane * 4;

    u64 acc[2][NCP][4];
#pragma unroll
    for (int r = 0; r < 2; r++)
#pragma unroll
        for (int c = 0; c < NCP; c++)
#pragma unroll
            for (int k = 0; k < 4; k++) acc[r][c][k] = 0ull;

    const float* inN = in + (size_t)n * CIN * HW;

    for (int c0 = 0; c0 < CIN; c0 += KC) {
        // ---- stage input slab: KC ch x 4 rows x 130 cols (halo, zero-pad)
        for (int i = tid; i < KC * 4 * 130; i += 256) {
            int kc  = i / 520;
            int rem = i % 520;
            int r   = rem / 130;
            int c   = rem % 130;
            int ci  = c0 + kc;
            int gh  = h0 - 1 + r;
            int gc  = c - 1;
            float v = 0.f;
            if (ci < CIN && gh >= 0 && gh < 128 && (unsigned)gc < 128u)
                v = inN[(size_t)ci * HW + gh * 128 + gc];
            s_in[kc][r][c] = v;
        }
        // ---- stage paired weights
        for (int i = tid; i < NCPG * KC * 9; i += 256) {
            int cpg = i / (KC * 9);
            int rem = i % (KC * 9);
            int kc  = rem / 9;
            int tap = rem % 9;
            int co0 = co_base + 2 * cpg;
            int ci  = c0 + kc;
            float v0 = 0.f, v1 = 0.f;
            if (ci < CIN) {
                if (co0     < COUT) v0 = wt[((size_t)co0       * CIN + ci) * 9 + tap];
                if (co0 + 1 < COUT) v1 = wt[((size_t)(co0 + 1) * CIN + ci) * 9 + tap];
            }
            s_w[cpg][rem] = pack2(v0, v1);
        }
        __syncthreads();

        for (int kc = 0; kc < KC; kc++) {
#pragma unroll
            for (int dh = 0; dh < 3; dh++) {
                // slab rows dh (for output row 0) and dh+1 (for output row 1)
                u64 dup[2][6];
#pragma unroll
                for (int rr = 0; rr < 2; rr++) {
                    const float* row = &s_in[kc][dh + rr][0];
                    float4 X = *(const float4*)(row + p0);
                    float2 Y = *(const float2*)(row + p0 + 4);
                    dup[rr][0] = pack2(X.x, X.x);
                    dup[rr][1] = pack2(X.y, X.y);
                    dup[rr][2] = pack2(X.z, X.z);
                    dup[rr][3] = pack2(X.w, X.w);
                    dup[rr][4] = pack2(Y.x, Y.x);
                    dup[rr][5] = pack2(Y.y, Y.y);
                }
#pragma unroll
                for (int dw = 0; dw < 3; dw++) {
#pragma unroll
                    for (int cp = 0; cp < NCP; cp++) {
                        u64 w = s_w[cg * NCP + cp][kc * 9 + dh * 3 + dw];
#pragma unroll
                        for (int orow = 0; orow < 2; orow++)
#pragma unroll
                            for (int px = 0; px < 4; px++)
                                fma2(acc[orow][cp][px], w, dup[orow][px + dw]);
                    }
                }
            }
        }
        __syncthreads();
    }

    // ---- epilogue: unpack, bias, activation, vectorized stores
#pragma unroll
    for (int orow = 0; orow < 2; orow++) {
#pragma unroll
        for (int cp = 0; cp < NCP; cp++) {
            int co0 = co_base + 2 * (cg * NCP + cp);
            float2 r0 = unpk(acc[orow][cp][0]);
            float2 r1 = unpk(acc[orow][cp][1]);
            float2 r2 = unpk(acc[orow][cp][2]);
            float2 r3 = unpk(acc[orow][cp][3]);
            size_t rowoff = (size_t)(h0 + orow) * 128 + p0;
            if (co0 < COUT) {
                float b = bias[co0];
                float4 o;
                o.x = apply_act(r0.x + b, ACT);
                o.y = apply_act(r1.x + b, ACT);
                o.z = apply_act(r2.x + b, ACT);
                o.w = apply_act(r3.x + b, ACT);
                *(float4*)&out[((size_t)n * COUT + co0) * HW + rowoff] = o;
            }
            if (co0 + 1 < COUT) {
                float b = bias[co0 + 1];
                float4 o;
                o.x = apply_act(r0.y + b, ACT);
                o.y = apply_act(r1.y + b, ACT);
                o.z = apply_act(r2.y + b, ACT);
                o.w = apply_act(r3.y + b, ACT);
                *(float4*)&out[((size_t)n * COUT + (co0 + 1)) * HW + rowoff] = o;
            }
        }
    }
}

// ---------------------------------------------------------------------------
// Scalar fallback conv (used only for tiny e3: 64->8).
// ---------------------------------------------------------------------------
template<int CIN, int COUT, int MT, int ACT>
__global__ __launch_bounds__(256)
void conv3x3(const float* __restrict__ in, const float* __restrict__ wt,
             const float* __restrict__ bias, float* __restrict__ out) {
    constexpr int KC  = 8;
    constexpr int NCO = MT / 8;

    __shared__ float s_in[KC][3][132];
    __shared__ float s_w [MT][KC * 9];

    const int n       = blockIdx.z;
    const int h       = blockIdx.x;
    const int co_base = blockIdx.y * MT;
    const int tid     = threadIdx.x;
    const int lane    = tid & 31;
    const int cg      = tid >> 5;

    float acc[NCO][4];
#pragma unroll
    for (int c = 0; c < NCO; c++)
#pragma unroll
        for (int k = 0; k < 4; k++) acc[c][k] = 0.f;

    const float* inN = in + (size_t)n * CIN * HW;

    for (int c0 = 0; c0 < CIN; c0 += KC) {
        for (int i = tid; i < KC * 3 * 130; i += 256) {
            int kc  = i / 390;
            int rem = i % 390;
            int r   = rem / 130;
            int c   = rem % 130;
            int ci  = c0 + kc;
            int gh  = h - 1 + r;
            int gc  = c - 1;
            float v = 0.f;
            if (ci < CIN && gh >= 0 && gh < 128 && gc >= 0 && gc < 128)
                v = inN[(size_t)ci * HW + gh * 128 + gc];
            s_in[kc][r][c] = v;
        }
        for (int i = tid; i < MT * KC * 9; i += 256) {
            int mt  = i / (KC * 9);
            int rem = i % (KC * 9);
            int kc  = rem / 9;
            int tap = rem % 9;
            int co  = co_base + mt;
            int ci  = c0 + kc;
            float v = 0.f;
            if (co < COUT && ci < CIN)
                v = wt[((size_t)co * CIN + ci) * 9 + tap];
            s_w[mt][rem] = v;
        }
        __syncthreads();

        for (int kc = 0; kc < KC; kc++) {
#pragma unroll
            for (int dh = 0; dh < 3; dh++) {
                float xin[12];
#pragma unroll
                for (int k = 0; k < 4; k++)
#pragma unroll
                    for (int d = 0; d < 3; d++)
                        xin[k * 3 + d] = s_in[kc][dh][lane + k * 32 + d];
#pragma unroll
                for (int dw = 0; dw < 3; dw++) {
#pragma unroll
                    for (int c = 0; c < NCO; c++) {
                        float wv = s_w[cg * NCO + c][kc * 9 + dh * 3 + dw];
#pragma unroll
                        for (int k = 0; k < 4; k++)
                            acc[c][k] = fmaf(wv, xin[k * 3 + dw], acc[c][k]);
                    }
                }
            }
        }
        __syncthreads();
    }

#pragma unroll
    for (int c = 0; c < NCO; c++) {
        int co = co_base + cg * NCO + c;
        if (co < COUT) {
            float b = bias[co];
#pragma unroll
            for (int k = 0; k < 4; k++) {
                float v = acc[c][k] + b;
                if (ACT == 1) v = fmaxf(v, 0.f);
                else if (ACT == 2) v = 1.f / (1.f + __expf(-v));
                out[((size_t)n * COUT + co) * HW + h * 128 + lane + k * 32] = v;
            }
        }
    }
}

// ---------------------------------------------------------------------------
// Vector quantizer (groups of 8 along W, torch .view semantics).
// ---------------------------------------------------------------------------
__global__ __launch_bounds__(256)
void vq_kernel(const float* __restrict__ z, const float* __restrict__ emb,
               float* __restrict__ q, double* __restrict__ part) {
    __shared__ float  s_e[512 * 8];
    __shared__ float  s_hn[512];
    __shared__ double s_red[256];

    const int tid = threadIdx.x;
    for (int i = tid; i < 4096; i += 256) s_e[i] = emb[i];
    __syncthreads();
    for (int k = tid; k < 512; k += 256) {
        float s = 0.f;
#pragma unroll
        for (int j = 0; j < 8; j++) { float e = s_e[k * 8 + j]; s += e * e; }
        s_hn[k] = 0.5f * s;
    }
    __syncthreads();

    const int base = blockIdx.x * 1024 + tid;
    float v[4][8];
#pragma unroll
    for (int u = 0; u < 4; u++) {
        int vi = base + u * 256;
        float4 a = ((const float4*)z)[vi * 2];
        float4 b = ((const float4*)z)[vi * 2 + 1];
        v[u][0] = a.x; v[u][1] = a.y; v[u][2] = a.z; v[u][3] = a.w;
        v[u][4] = b.x; v[u][5] = b.y; v[u][6] = b.z; v[u][7] = b.w;
    }

    float best[4] = {3.4e38f, 3.4e38f, 3.4e38f, 3.4e38f};
    int   bk[4]   = {0, 0, 0, 0};
    for (int k = 0; k < 512; k++) {
        float e0 = s_e[k * 8 + 0], e1 = s_e[k * 8 + 1], e2 = s_e[k * 8 + 2], e3 = s_e[k * 8 + 3];
        float e4 = s_e[k * 8 + 4], e5 = s_e[k * 8 + 5], e6 = s_e[k * 8 + 6], e7 = s_e[k * 8 + 7];
        float hn = s_hn[k];
#pragma unroll
        for (int u = 0; u < 4; u++) {
            float dot = e0 * v[u][0] + e1 * v[u][1] + e2 * v[u][2] + e3 * v[u][3]
                      + e4 * v[u][4] + e5 * v[u][5] + e6 * v[u][6] + e7 * v[u][7];
            float sc = hn - dot;
            if (sc < best[u]) { best[u] = sc; bk[u] = k; }
        }
    }

    float sq = 0.f;
#pragma unroll
    for (int u = 0; u < 4; u++) {
        int vi = base + u * 256;
        int kb = bk[u];
        float4 o1, o2;
        o1.x = s_e[kb * 8 + 0]; o1.y = s_e[kb * 8 + 1];
        o1.z = s_e[kb * 8 + 2]; o1.w = s_e[kb * 8 + 3];
        o2.x = s_e[kb * 8 + 4]; o2.y = s_e[kb * 8 + 5];
        o2.z = s_e[kb * 8 + 6]; o2.w = s_e[kb * 8 + 7];
#pragma unroll
        for (int j = 0; j < 8; j++) {
            float d = s_e[kb * 8 + j] - v[u][j];
            sq += d * d;
        }
        ((float4*)q)[vi * 2]     = o1;
        ((float4*)q)[vi * 2 + 1] = o2;
    }

    s_red[tid] = (double)sq;
    __syncthreads();
    for (int o = 128; o > 0; o >>= 1) {
        if (tid < o) s_red[tid] += s_red[tid + o];
        __syncthreads();
    }
    if (tid == 0) part[blockIdx.x] = s_red[0];
}

__global__ void finalize_loss(const double* __restrict__ part, float* __restrict__ outp) {
    __shared__ double s[256];
    int tid = threadIdx.x;
    s[tid] = part[tid];
    __syncthreads();
    for (int o = 128; o > 0; o >>= 1) {
        if (tid < o) s[tid] += s[tid + o];
        __syncthreads();
    }
    if (tid == 0) *outp = (float)(1.25 * s[0] / 2097152.0);
}

// ---------------------------------------------------------------------------
extern "C" void kernel_launch(void* const* d_in, const int* in_sizes, int n_in,
                              void* d_out, int out_size) {
    (void)in_sizes; (void)n_in;
    const float* x   = (const float*)d_in[0];
    const float* e1w = (const float*)d_in[1];
    const float* e1b = (const float*)d_in[2];
    const float* e2w = (const float*)d_in[3];
    const float* e2b = (const float*)d_in[4];
    const float* e3w = (const float*)d_in[5];
    const float* e3b = (const float*)d_in[6];
    const float* emb = (const float*)d_in[7];
    const float* d1w = (const float*)d_in[8];
    const float* d1b = (const float*)d_in[9];
    const float* d2w = (const float*)d_in[10];
    const float* d2b = (const float*)d_in[11];
    const float* d3w = (const float*)d_in[12];
    const float* d3b = (const float*)d_in[13];
    float* out = (float*)d_out;

    void *z1, *z2, *z3, *q, *y1, *y2, *w1e, *w2e, *w3e, *part;
    cudaGetSymbolAddress(&z1,  g_z1);
    cudaGetSymbolAddress(&z2,  g_z2);
    cudaGetSymbolAddress(&z3,  g_z3);
    cudaGetSymbolAddress(&q,   g_q);
    cudaGetSymbolAddress(&y1,  g_y1);
    cudaGetSymbolAddress(&y2,  g_y2);
    cudaGetSymbolAddress(&w1e, g_w1e);
    cudaGetSymbolAddress(&w2e, g_w2e);
    cudaGetSymbolAddress(&w3e, g_w3e);
    cudaGetSymbolAddress(&part, g_part);

    // decoder weight prep (flip + IO swap)
    transpose_wt<<<(8 * 64 * 9 + 255) / 256, 256>>>(d1w, (float*)w1e, 8, 64);
    transpose_wt<<<(64 * 128 * 9 + 255) / 256, 256>>>(d2w, (float*)w2e, 64, 128);
    transpose_wt<<<(128 * 156 * 9 + 255) / 256, 256>>>(d3w, (float*)w3e, 128, 156);

    // encoder
    conv3x3p<156, 128, 64, 1, 0><<<dim3(64, 2, 16), 256>>>(x, e1w, e1b, (float*)z1);
    conv3x3p<128,  64, 64, 1, 0><<<dim3(64, 1, 16), 256>>>((float*)z1, e2w, e2b, (float*)z2);
    conv3x3< 64,   8,  8, 1><<<dim3(128, 1, 16), 256>>>((float*)z2, e3w, e3b, (float*)z3);

    // vector quantizer + loss partials
    vq_kernel<<<256, 256>>>((const float*)z3, emb, (float*)q, (double*)part);

    // decoder
    conv3x3p<  8,  64, 64, 1, 0><<<dim3(64, 1, 16), 256>>>((float*)q,  (float*)w1e, d1b, (float*)y1);
    conv3x3p< 64, 128, 64, 1, 0><<<dim3(64, 2, 16), 256>>>((float*)y1, (float*)w2e, d2b, (float*)y2);
    // d3: co 0..127 in two MT=64 blocks, co 128..159 in one MT=32 tail
    conv3x3p<128, 156, 64, 2, 0>  <<<dim3(64, 2, 16), 256>>>((float*)y2, (float*)w3e, d3b, out);
    conv3x3p<128, 156, 32, 2, 128><<<dim3(64, 1, 16), 256>>>((float*)y2, (float*)w3e, d3b, out);

    finalize_loss<<<1, 256>>>((const double*)part, out + (out_size - 1));
}